// round 1
// baseline (speedup 1.0000x reference)
#include <cuda_runtime.h>
#include <cuda_bf16.h>
#include <cuda_fp8.h>
#include <mma.h>

using namespace nvcuda;

#define T_DIM 8192
#define K_DIM 2048
#define N_DIM 2048
#define FP8_MAX_F 448.0f

// ---------------- scratch (device globals: no runtime allocation) ----------
__device__ unsigned g_amax_x_bits;
__device__ unsigned g_amax_w_bits;
__device__ __nv_bfloat16 g_xq[(size_t)T_DIM * K_DIM];   // quantized x (exact fp8 values in bf16)
__device__ __nv_bfloat16 g_wq[(size_t)N_DIM * K_DIM];   // quantized weight, [N,K] layout
__device__ float g_bias_rep[16 * N_DIM];                // bias[n]/scale replicated over 16 rows

// ---------------- helpers ---------------------------------------------------
__device__ __forceinline__ float fp8_roundtrip(float v) {
    __nv_fp8_storage_t s = __nv_cvt_float_to_fp8(v, __NV_SATFINITE, __NV_E4M3);
    __half_raw hr = __nv_cvt_fp8_to_halfraw(s, __NV_E4M3);
    return __half2float(*reinterpret_cast<__half*>(&hr));
}

// ---------------- kernels ---------------------------------------------------
__global__ void init_kernel() {
    g_amax_x_bits = 0u;
    g_amax_w_bits = 0u;
}

__global__ void amax_kernel(const float4* __restrict__ p, int n4, int which) {
    float m = 0.f;
    for (int i = blockIdx.x * blockDim.x + threadIdx.x; i < n4; i += gridDim.x * blockDim.x) {
        float4 v = p[i];
        m = fmaxf(m, fmaxf(fmaxf(fabsf(v.x), fabsf(v.y)), fmaxf(fabsf(v.z), fabsf(v.w))));
    }
    #pragma unroll
    for (int o = 16; o; o >>= 1) m = fmaxf(m, __shfl_xor_sync(0xffffffffu, m, o));
    __shared__ float sm[32];
    int lane = threadIdx.x & 31, w = threadIdx.x >> 5;
    if (lane == 0) sm[w] = m;
    __syncthreads();
    if (w == 0) {
        m = (lane < (int)(blockDim.x >> 5)) ? sm[lane] : 0.f;
        #pragma unroll
        for (int o = 16; o; o >>= 1) m = fmaxf(m, __shfl_xor_sync(0xffffffffu, m, o));
        if (lane == 0)
            atomicMax(which ? &g_amax_w_bits : &g_amax_x_bits, __float_as_uint(m));
    }
}

__global__ void quant_kernel(const float4* __restrict__ src, __nv_bfloat16* __restrict__ dst,
                             int n4, int which) {
    float amax = __uint_as_float(which ? g_amax_w_bits : g_amax_x_bits);
    float inv = fmaxf(amax / FP8_MAX_F, 1e-12f);
    float r = 1.0f / inv;
    __nv_bfloat162* d2 = reinterpret_cast<__nv_bfloat162*>(dst);
    for (int i = blockIdx.x * blockDim.x + threadIdx.x; i < n4; i += gridDim.x * blockDim.x) {
        float4 v = src[i];
        __nv_bfloat16 q0 = __float2bfloat16(fp8_roundtrip(v.x * r));
        __nv_bfloat16 q1 = __float2bfloat16(fp8_roundtrip(v.y * r));
        __nv_bfloat16 q2 = __float2bfloat16(fp8_roundtrip(v.z * r));
        __nv_bfloat16 q3 = __float2bfloat16(fp8_roundtrip(v.w * r));
        d2[2 * i + 0] = __nv_bfloat162(q0, q1);
        d2[2 * i + 1] = __nv_bfloat162(q2, q3);
    }
}

__global__ void bias_prep_kernel(const float* __restrict__ bias) {
    int n = blockIdx.x * blockDim.x + threadIdx.x;
    if (n < N_DIM) {
        float sx = fmaxf(__uint_as_float(g_amax_x_bits) / FP8_MAX_F, 1e-12f);
        float sw = fmaxf(__uint_as_float(g_amax_w_bits) / FP8_MAX_F, 1e-12f);
        float b = bias[n] / (sx * sw);
        #pragma unroll
        for (int r = 0; r < 16; r++) g_bias_rep[r * N_DIM + n] = b;
    }
}

#define BM 128
#define BN 128
#define BK 32
#define SPAD 8

__global__ __launch_bounds__(256) void gemm_kernel(float* __restrict__ out) {
    __shared__ __nv_bfloat16 As[BM][BK + SPAD];
    __shared__ __nv_bfloat16 Bs[BN][BK + SPAD];

    const int warp = threadIdx.x >> 5;
    const int wm = warp >> 2;   // 0..1  -> 64-row slab
    const int wn = warp & 3;    // 0..3  -> 32-col slab
    const int bm = blockIdx.y * BM;
    const int bn = blockIdx.x * BN;

    float sx = fmaxf(__uint_as_float(g_amax_x_bits) / FP8_MAX_F, 1e-12f);
    float sw = fmaxf(__uint_as_float(g_amax_w_bits) / FP8_MAX_F, 1e-12f);
    float scale = sx * sw;

    wmma::fragment<wmma::accumulator, 16, 16, 16, float> acc[4][2];
    #pragma unroll
    for (int i = 0; i < 4; i++)
        #pragma unroll
        for (int j = 0; j < 2; j++)
            wmma::load_matrix_sync(acc[i][j], &g_bias_rep[bn + wn * 32 + j * 16],
                                   N_DIM, wmma::mem_row_major);

    for (int kt = 0; kt < K_DIM; kt += BK) {
        // cooperative tile loads: 512 16B vectors per operand, 2 per thread
        #pragma unroll
        for (int s = 0; s < 2; s++) {
            int v = threadIdx.x + s * 256;   // 0..511
            int r = v >> 2;                  // 0..127
            int c = (v & 3) * 8;             // 0,8,16,24
            *reinterpret_cast<uint4*>(&As[r][c]) =
                *reinterpret_cast<const uint4*>(&g_xq[(size_t)(bm + r) * K_DIM + kt + c]);
            *reinterpret_cast<uint4*>(&Bs[r][c]) =
                *reinterpret_cast<const uint4*>(&g_wq[(size_t)(bn + r) * K_DIM + kt + c]);
        }
        __syncthreads();

        #pragma unroll
        for (int kk = 0; kk < BK; kk += 16) {
            wmma::fragment<wmma::matrix_a, 16, 16, 16, __nv_bfloat16, wmma::row_major> a[4];
            wmma::fragment<wmma::matrix_b, 16, 16, 16, __nv_bfloat16, wmma::col_major> b[2];
            #pragma unroll
            for (int i = 0; i < 4; i++)
                wmma::load_matrix_sync(a[i], &As[wm * 64 + i * 16][kk], BK + SPAD);
            #pragma unroll
            for (int j = 0; j < 2; j++)
                wmma::load_matrix_sync(b[j], &Bs[wn * 32 + j * 16][kk], BK + SPAD);
            #pragma unroll
            for (int i = 0; i < 4; i++)
                #pragma unroll
                for (int j = 0; j < 2; j++)
                    wmma::mma_sync(acc[i][j], a[i], b[j], acc[i][j]);
        }
        __syncthreads();
    }

    #pragma unroll
    for (int i = 0; i < 4; i++)
        #pragma unroll
        for (int j = 0; j < 2; j++) {
            #pragma unroll
            for (int e = 0; e < acc[i][j].num_elements; e++) acc[i][j].x[e] *= scale;
            wmma::store_matrix_sync(
                &out[(size_t)(bm + wm * 64 + i * 16) * N_DIM + bn + wn * 32 + j * 16],
                acc[i][j], N_DIM, wmma::mem_row_major);
        }
}

// ---------------- launcher --------------------------------------------------
extern "C" void kernel_launch(void* const* d_in, const int* in_sizes, int n_in,
                              void* d_out, int out_size) {
    const float* x      = (const float*)d_in[0];   // [4,2048,2048]
    const float* weight = (const float*)d_in[1];   // [2048,2048]
    const float* bias   = (const float*)d_in[2];   // [2048]
    float* out = (float*)d_out;

    const int nx4 = (T_DIM * K_DIM) / 4;           // 4,194,304
    const int nw4 = (N_DIM * K_DIM) / 4;           // 1,048,576

    init_kernel<<<1, 1>>>();
    amax_kernel<<<1024, 256>>>((const float4*)x, nx4, 0);
    amax_kernel<<<512, 256>>>((const float4*)weight, nw4, 1);

    __nv_bfloat16* xq_ptr = nullptr;
    __nv_bfloat16* wq_ptr = nullptr;
    cudaGetSymbolAddress((void**)&xq_ptr, g_xq);
    cudaGetSymbolAddress((void**)&wq_ptr, g_wq);

    quant_kernel<<<2048, 256>>>((const float4*)x, xq_ptr, nx4, 0);
    quant_kernel<<<1024, 256>>>((const float4*)weight, wq_ptr, nw4, 1);
    bias_prep_kernel<<<(N_DIM + 255) / 256, 256>>>(bias);

    dim3 grid(N_DIM / BN, T_DIM / BM);   // (16, 64)
    gemm_kernel<<<grid, 256>>>(out);
}

// round 8
// speedup vs baseline: 1.5169x; 1.5169x over previous
#include <cuda_runtime.h>
#include <cuda_bf16.h>
#include <cuda_fp8.h>
#include <cstdint>

#define T_DIM 8192
#define K_DIM 2048
#define N_DIM 2048
#define FP8_MAX_F 448.0f

// ---------------- scratch (device globals: no runtime allocation) ----------
__device__ unsigned g_amax_x_bits;
__device__ unsigned g_amax_w_bits;
__device__ uint8_t g_xq[(size_t)T_DIM * K_DIM];   // fp8 e4m3 x, [T,K] row-major
__device__ uint8_t g_wq[(size_t)N_DIM * K_DIM];   // fp8 e4m3 weight, [N,K] row-major

// ---------------- helpers ----------------------------------------------------
__device__ __forceinline__ uint32_t smem_to_u32(const void* p) {
    uint32_t a;
    asm("{ .reg .u64 t; cvta.to.shared.u64 t, %1; cvt.u32.u64 %0, t; }" : "=r"(a) : "l"(p));
    return a;
}

// 128B-line chunk swizzle: XOR 16B-chunk index with (line index % 8).
// Conflict-free for ldmatrix (8 rows x 16B) and for cp.async 16B stores.
#define SWZ(o) ((o) ^ ((((o) >> 7) & 7) << 4))

#define CP_ASYNC16(smem_addr, gptr) \
    asm volatile("cp.async.cg.shared.global [%0], [%1], 16;" \
                 :: "r"(smem_addr), "l"(gptr) : "memory")
#define CP_COMMIT() asm volatile("cp.async.commit_group;" ::: "memory")
#define CP_WAIT2()  asm volatile("cp.async.wait_group 2;" ::: "memory")

#define LDMATRIX_X4(r0, r1, r2, r3, addr) \
    asm volatile("ldmatrix.sync.aligned.m8n8.x4.shared.b16 {%0,%1,%2,%3}, [%4];" \
                 : "=r"(r0), "=r"(r1), "=r"(r2), "=r"(r3) : "r"(addr))

#define MMA_FP8(c, a, b0v, b1v) \
    asm volatile("mma.sync.aligned.m16n8k32.row.col.f32.e4m3.e4m3.f32 " \
                 "{%0,%1,%2,%3}, {%4,%5,%6,%7}, {%8,%9}, {%0,%1,%2,%3};" \
                 : "+f"((c)[0]), "+f"((c)[1]), "+f"((c)[2]), "+f"((c)[3]) \
                 : "r"((a)[0]), "r"((a)[1]), "r"((a)[2]), "r"((a)[3]), \
                   "r"(b0v), "r"(b1v))

// ---------------- small kernels ----------------------------------------------
__global__ void init_kernel() {
    g_amax_x_bits = 0u;
    g_amax_w_bits = 0u;
}

__global__ void amax_kernel(const float4* __restrict__ p, int n4, int which) {
    float m = 0.f;
    for (int i = blockIdx.x * blockDim.x + threadIdx.x; i < n4; i += gridDim.x * blockDim.x) {
        float4 v = p[i];
        m = fmaxf(m, fmaxf(fmaxf(fabsf(v.x), fabsf(v.y)), fmaxf(fabsf(v.z), fabsf(v.w))));
    }
    #pragma unroll
    for (int o = 16; o; o >>= 1) m = fmaxf(m, __shfl_xor_sync(0xffffffffu, m, o));
    __shared__ float sm[32];
    int lane = threadIdx.x & 31, w = threadIdx.x >> 5;
    if (lane == 0) sm[w] = m;
    __syncthreads();
    if (w == 0) {
        m = (lane < (int)(blockDim.x >> 5)) ? sm[lane] : 0.f;
        #pragma unroll
        for (int o = 16; o; o >>= 1) m = fmaxf(m, __shfl_xor_sync(0xffffffffu, m, o));
        if (lane == 0)
            atomicMax(which ? &g_amax_w_bits : &g_amax_x_bits, __float_as_uint(m));
    }
}

__global__ void quant_kernel(const float4* __restrict__ src, uint8_t* __restrict__ dst,
                             int n4, int which) {
    float amax = __uint_as_float(which ? g_amax_w_bits : g_amax_x_bits);
    float inv = fmaxf(amax / FP8_MAX_F, 1e-12f);
    float r = 1.0f / inv;
    uint32_t* d = reinterpret_cast<uint32_t*>(dst);
    for (int i = blockIdx.x * blockDim.x + threadIdx.x; i < n4; i += gridDim.x * blockDim.x) {
        float4 v = src[i];
        __nv_fp8x2_storage_t lo =
            __nv_cvt_float2_to_fp8x2(make_float2(v.x * r, v.y * r), __NV_SATFINITE, __NV_E4M3);
        __nv_fp8x2_storage_t hi =
            __nv_cvt_float2_to_fp8x2(make_float2(v.z * r, v.w * r), __NV_SATFINITE, __NV_E4M3);
        d[i] = (uint32_t)lo | ((uint32_t)hi << 16);
    }
}

// ---------------- fp8 mma.sync GEMM ------------------------------------------
#define BM 128
#define BN 128
#define BK 64
#define KT (K_DIM / BK)          // 32 k-tiles
#define STAGES 4
#define STAGE_BYTES (BM * BK + BN * BK)   // 16384
#define B_OFF (BM * BK)                    // 8192
#define SMEM_TOTAL (STAGES * STAGE_BYTES)  // 65536

__global__ void __launch_bounds__(256, 2) gemm_kernel(float* __restrict__ out,
                                                      const float* __restrict__ bias) {
    extern __shared__ char smem[];
    const uint32_t sbase = smem_to_u32(smem);
    const int tid = threadIdx.x;
    const int wid = tid >> 5, lid = tid & 31;
    const int wm = wid >> 2;              // 0..1  (64-row slab)
    const int wn = wid & 3;               // 0..3  (32-col slab)
    const int bm = blockIdx.y * BM;
    const int bn = blockIdx.x * BN;

    // ---- gmem -> smem mapping (cp.async, 16B granularity) ----
    // per stage: A 128 rows x 4 chunks, B 128 rows x 4 chunks; 2 tasks/operand/thread
    const int lrow = tid >> 2;            // 0..63 (+64 for task 1)
    const int lcol = (tid & 3) * 16;      // 0/16/32/48
    const uint8_t* gA = g_xq + (size_t)(bm + lrow) * K_DIM + lcol;
    const uint8_t* gB = g_wq + (size_t)(bn + lrow) * K_DIM + lcol;
    uint32_t sA0 = SWZ((uint32_t)(lrow * BK + lcol));
    uint32_t sA1 = SWZ((uint32_t)((lrow + 64) * BK + lcol));

    // ---- ldmatrix per-lane addressing ----
    const int g8 = lid >> 3, l8 = lid & 7;
    const uint32_t a_row = wm * 64 + (g8 & 1) * 8 + l8;   // + i*16
    const uint32_t a_col = (g8 >> 1) * 16;                // + kk
    const uint32_t b_row = wn * 32 + (g8 >> 1) * 8 + l8;  // + jp (0 or 16)
    const uint32_t b_col = (g8 & 1) * 16;                 // + kk

    float acc[4][4][4];
    #pragma unroll
    for (int i = 0; i < 4; i++)
        #pragma unroll
        for (int j = 0; j < 4; j++)
            #pragma unroll
            for (int e = 0; e < 4; e++) acc[i][j][e] = 0.f;

    // ---- prologue: stages 0..2 ----
    #pragma unroll
    for (int s = 0; s < STAGES - 1; s++) {
        uint32_t st = sbase + s * STAGE_BYTES;
        CP_ASYNC16(st + sA0, gA + (size_t)s * BK);
        CP_ASYNC16(st + sA1, gA + (size_t)64 * K_DIM + (size_t)s * BK);
        CP_ASYNC16(st + B_OFF + sA0, gB + (size_t)s * BK);
        CP_ASYNC16(st + B_OFF + sA1, gB + (size_t)64 * K_DIM + (size_t)s * BK);
        CP_COMMIT();
    }

    for (int t = 0; t < KT; t++) {
        CP_WAIT2();
        __syncthreads();

        // issue loads for tile t+3 into slot (t+3)%4 (consumed slot (t-1)%4)
        if (t + STAGES - 1 < KT) {
            const int tt = t + STAGES - 1;
            uint32_t st = sbase + (tt & (STAGES - 1)) * STAGE_BYTES;
            CP_ASYNC16(st + sA0, gA + (size_t)tt * BK);
            CP_ASYNC16(st + sA1, gA + (size_t)64 * K_DIM + (size_t)tt * BK);
            CP_ASYNC16(st + B_OFF + sA0, gB + (size_t)tt * BK);
            CP_ASYNC16(st + B_OFF + sA1, gB + (size_t)64 * K_DIM + (size_t)tt * BK);
        }
        CP_COMMIT();

        // compute on slot t%4
        const uint32_t stA = sbase + (t & (STAGES - 1)) * STAGE_BYTES;
        const uint32_t stB = stA + B_OFF;
        #pragma unroll
        for (int kk = 0; kk < BK; kk += 32) {
            uint32_t b[4][2];
            #pragma unroll
            for (int jh = 0; jh < 2; jh++) {   // jp = 0, 16 -> frags (2jh), (2jh+1)
                uint32_t r0, r1, r2, r3;
                uint32_t off = (b_row + jh * 16) * BK + kk + b_col;
                LDMATRIX_X4(r0, r1, r2, r3, stB + SWZ(off));
                b[2 * jh][0] = r0;  b[2 * jh][1] = r1;
                b[2 * jh + 1][0] = r2;  b[2 * jh + 1][1] = r3;
            }
            #pragma unroll
            for (int i = 0; i < 4; i++) {
                uint32_t a[4];
                uint32_t off = (a_row + i * 16) * BK + kk + a_col;
                LDMATRIX_X4(a[0], a[1], a[2], a[3], stA + SWZ(off));
                #pragma unroll
                for (int j = 0; j < 4; j++)
                    MMA_FP8(acc[i][j], a, b[j][0], b[j][1]);
            }
        }
    }

    // ---- epilogue: scale + bias ----
    const float sx = fmaxf(__uint_as_float(g_amax_x_bits) / FP8_MAX_F, 1e-12f);
    const float sw = fmaxf(__uint_as_float(g_amax_w_bits) / FP8_MAX_F, 1e-12f);
    const float scale = sx * sw;

    #pragma unroll
    for (int i = 0; i < 4; i++) {
        const int m0 = bm + wm * 64 + i * 16 + (lid >> 2);
        #pragma unroll
        for (int j = 0; j < 4; j++) {
            const int n0 = bn + wn * 32 + j * 8 + (lid & 3) * 2;
            const float2 b2 = *reinterpret_cast<const float2*>(&bias[n0]);
            float2 o0, o1;
            o0.x = acc[i][j][0] * scale + b2.x;
            o0.y = acc[i][j][1] * scale + b2.y;
            o1.x = acc[i][j][2] * scale + b2.x;
            o1.y = acc[i][j][3] * scale + b2.y;
            *reinterpret_cast<float2*>(&out[(size_t)m0 * N_DIM + n0]) = o0;
            *reinterpret_cast<float2*>(&out[(size_t)(m0 + 8) * N_DIM + n0]) = o1;
        }
    }
}

// ---------------- launcher ----------------------------------------------------
extern "C" void kernel_launch(void* const* d_in, const int* in_sizes, int n_in,
                              void* d_out, int out_size) {
    const float* x      = (const float*)d_in[0];   // [4,2048,2048]
    const float* weight = (const float*)d_in[1];   // [2048,2048]
    const float* bias   = (const float*)d_in[2];   // [2048]
    float* out = (float*)d_out;

    const int nx4 = (T_DIM * K_DIM) / 4;
    const int nw4 = (N_DIM * K_DIM) / 4;

    uint8_t* xq_ptr = nullptr;
    uint8_t* wq_ptr = nullptr;
    cudaGetSymbolAddress((void**)&xq_ptr, g_xq);
    cudaGetSymbolAddress((void**)&wq_ptr, g_wq);

    cudaFuncSetAttribute(gemm_kernel, cudaFuncAttributeMaxDynamicSharedMemorySize, SMEM_TOTAL);

    init_kernel<<<1, 1>>>();
    amax_kernel<<<1024, 256>>>((const float4*)x, nx4, 0);
    amax_kernel<<<512, 256>>>((const float4*)weight, nw4, 1);
    quant_kernel<<<2048, 256>>>((const float4*)x, xq_ptr, nx4, 0);
    quant_kernel<<<1024, 256>>>((const float4*)weight, wq_ptr, nw4, 1);

    dim3 grid(N_DIM / BN, T_DIM / BM);   // (16, 64)
    gemm_kernel<<<grid, 256, SMEM_TOTAL>>>(out, bias);
}